// round 1
// baseline (speedup 1.0000x reference)
#include <cuda_runtime.h>
#include <math.h>

#define Bn 128
#define Tn 256
#define Ln 64
#define Sn 25
#define Hn 128

#define W1S 132   // stride (floats) for sW1 [64][132]
#define W2S 68    // stride for sW2 [128][68]
#define ZS  68    // stride for sZ  [32][68]
#define THS 132   // stride for sTh [32][132]

#define ZF_SZ  52428800   // 25*128*256*64
#define M_SZ   2097152    // 128*256*64

// smem layout (floats)
#define OFF_W1  0
#define OFF_W2  (OFF_W1 + 64*W1S)      // 8448
#define OFF_Z   (OFF_W2 + 128*W2S)     // +8704
#define OFF_TH  (OFF_Z  + 32*ZS)       // +2176
#define OFF_P   (OFF_TH + 32*THS)      // +4224
#define OFF_MTH (OFF_P  + 32*ZS)       // +2176
#define OFF_B1  (OFF_MTH+ 32*ZS)       // +2176
#define OFF_B2  (OFF_B1 + 128)
#define OFF_Q   (OFF_B2 + 64)
#define OFF_MF  (OFF_Q  + 64)
#define OFF_SPF (OFF_MF + 64)
#define OFF_S1  (OFF_SPF+ 64)
#define OFF_S2  (OFF_S1 + 256)
#define SMEM_FLOATS (OFF_S2 + 256)
#define SMEM_BYTES (SMEM_FLOATS * 4)

__device__ __forceinline__ float tanh_fast(float x) {
    float y;
    asm("tanh.approx.f32 %0, %1;" : "=f"(y) : "f"(x));
    return y;
}

__global__ __launch_bounds__(256, 1)
void nlf_kernel(const float* __restrict__ k_in,
                const float* __restrict__ K_in,
                const float* __restrict__ noise,
                const float* __restrict__ logQ,
                const float* __restrict__ m0,
                const float* __restrict__ logQ0,
                const float* __restrict__ W1,
                const float* __restrict__ b1,
                const float* __restrict__ W2,
                const float* __restrict__ b2,
                float* __restrict__ out)
{
    extern __shared__ float sm[];
    float* sW1 = sm + OFF_W1;   // [64][132]  W1[k][h]
    float* sW2 = sm + OFF_W2;   // [128][68]  W2[k][l]
    float* sZ  = sm + OFF_Z;    // [32][68]   z[s][l]   (rows 25..31 stay 0)
    float* sTh = sm + OFF_TH;   // [32][132]  tanh-out[s][h]
    float* sPp = sm + OFF_P;    // [32][68]   GEMM2 partial (k-half 1)
    float* sMt = sm + OFF_MTH;  // [32][68]   m_th[s][l]
    float* sB1 = sm + OFF_B1;
    float* sB2 = sm + OFF_B2;
    float* sQ  = sm + OFF_Q;
    float* sMf = sm + OFF_MF;
    float* sSPf= sm + OFF_SPF;
    float* sS1 = sm + OFF_S1;   // [4][64]
    float* sS2 = sm + OFF_S2;   // [4][64]

    const int tid = threadIdx.x;
    const int b   = blockIdx.x;

    // --- load weights / biases into smem, zero z buffer ---
    for (int i = tid; i < 64*128; i += 256) {
        int kk = i >> 7, h = i & 127;
        sW1[kk*W1S + h] = W1[i];
    }
    for (int i = tid; i < 128*64; i += 256) {
        int kk = i >> 6, l = i & 63;
        sW2[kk*W2S + l] = W2[i];
    }
    if (tid < 128) sB1[tid] = b1[tid];
    if (tid < 64)  sB2[tid] = b2[tid];
    for (int i = tid; i < 32*ZS; i += 256) sZ[i] = 0.0f;

    // --- t = 0 init (per-l, 64 threads) ---
    if (tid < 64) {
        int l = tid;
        float Qd = log1pf(expf(logQ[l]));
        sQ[l] = Qd;
        float P0 = log1pf(expf(logQ0[l]));
        float J0 = 1.0f / P0;
        float h0 = J0 * m0[l];
        int  go  = (b*Tn + 0)*Ln + l;
        float Kv = K_in[go];
        float kv = k_in[go];
        float Jf = J0 + Kv;
        float Pf = 1.0f / Jf;
        float mf = Pf * (h0 + kv);
        out[ZF_SZ + 0*M_SZ + go] = mf;
        out[ZF_SZ + 1*M_SZ + go] = m0[l];
        out[ZF_SZ + 2*M_SZ + go] = Pf;
        out[ZF_SZ + 3*M_SZ + go] = P0;
        sMf[l]  = mf;
        sSPf[l] = sqrtf(Pf);
    }
    __syncthreads();

    // --- z update for t = 0 ---
    {
        const int t = 0;
        for (int idx = tid; idx < Sn*Ln; idx += 256) {
            int s = idx >> 6, l = idx & 63;
            float w  = noise[((t*Sn + s)*Bn + b)*Ln + l];
            float zv = sMf[l] + sSPf[l] * w;
            sZ[s*ZS + l] = zv;
            out[((s*Bn + b)*Tn + t)*Ln + l] = zv;
        }
    }

    // GEMM1 thread mapping: hx in [0,32) -> 4 consecutive h; sg in [0,8) -> s = sg+8i
    const int hx = tid & 31;
    const int sg = tid >> 5;
    // GEMM2 mapping: split-k halves of 128 threads; lx -> 4 consecutive l; sg2 -> s = sg2+8i
    const int half = tid >> 7;
    const int r2   = tid & 127;
    const int lx   = r2 & 15;
    const int sg2  = r2 >> 4;

    for (int t = 1; t < Tn; t++) {
        __syncthreads();

        // ---------------- GEMM1: th = tanh(z @ W1 + b1), [32 x 128] ----------------
        {
            float acc[4][4];
            #pragma unroll
            for (int i = 0; i < 4; i++)
                #pragma unroll
                for (int j = 0; j < 4; j++)
                    acc[i][j] = sB1[hx*4 + j];

            #pragma unroll 4
            for (int k = 0; k < 64; k++) {
                float4 w = *(const float4*)&sW1[k*W1S + hx*4];
                #pragma unroll
                for (int i = 0; i < 4; i++) {
                    float zv = sZ[(sg + 8*i)*ZS + k];
                    acc[i][0] = fmaf(zv, w.x, acc[i][0]);
                    acc[i][1] = fmaf(zv, w.y, acc[i][1]);
                    acc[i][2] = fmaf(zv, w.z, acc[i][2]);
                    acc[i][3] = fmaf(zv, w.w, acc[i][3]);
                }
            }
            #pragma unroll
            for (int i = 0; i < 4; i++) {
                float4 rr;
                rr.x = tanh_fast(acc[i][0]);
                rr.y = tanh_fast(acc[i][1]);
                rr.z = tanh_fast(acc[i][2]);
                rr.w = tanh_fast(acc[i][3]);
                *(float4*)&sTh[(sg + 8*i)*THS + hx*4] = rr;
            }
        }
        __syncthreads();

        // ---------------- GEMM2: m_th = z + th @ W2 + b2, [32 x 64], split-k ----------------
        {
            float acc[4][4];
            #pragma unroll
            for (int i = 0; i < 4; i++)
                #pragma unroll
                for (int j = 0; j < 4; j++)
                    acc[i][j] = 0.0f;

            const int k0 = half * 64;
            #pragma unroll 4
            for (int kk = 0; kk < 64; kk++) {
                int k = k0 + kk;
                float4 w = *(const float4*)&sW2[k*W2S + lx*4];
                #pragma unroll
                for (int i = 0; i < 4; i++) {
                    float tv = sTh[(sg2 + 8*i)*THS + k];
                    acc[i][0] = fmaf(tv, w.x, acc[i][0]);
                    acc[i][1] = fmaf(tv, w.y, acc[i][1]);
                    acc[i][2] = fmaf(tv, w.z, acc[i][2]);
                    acc[i][3] = fmaf(tv, w.w, acc[i][3]);
                }
            }
            if (half == 1) {
                #pragma unroll
                for (int i = 0; i < 4; i++) {
                    float4 rr = make_float4(acc[i][0], acc[i][1], acc[i][2], acc[i][3]);
                    *(float4*)&sPp[(sg2 + 8*i)*ZS + lx*4] = rr;
                }
            }
            __syncthreads();
            if (half == 0) {
                #pragma unroll
                for (int i = 0; i < 4; i++) {
                    int s = sg2 + 8*i;
                    float4 p = *(const float4*)&sPp[s*ZS + lx*4];
                    float4 z4 = *(const float4*)&sZ[s*ZS + lx*4];
                    float4 b4 = *(const float4*)&sB2[lx*4];
                    float4 m;
                    m.x = acc[i][0] + p.x + b4.x + z4.x;
                    m.y = acc[i][1] + p.y + b4.y + z4.y;
                    m.z = acc[i][2] + p.z + b4.z + z4.z;
                    m.w = acc[i][3] + p.w + b4.w + z4.w;
                    *(float4*)&sMt[s*ZS + lx*4] = m;
                }
            }
        }
        __syncthreads();

        // ---------------- moment reduction over s < 25 ----------------
        {
            int l = tid & 63, q = tid >> 6;
            float s1 = 0.0f, s2 = 0.0f;
            int smax = min(8*q + 8, Sn);
            for (int s = 8*q; s < smax; s++) {
                float v = sMt[s*ZS + l];
                s1 += v;
                s2 = fmaf(v, v, s2);
            }
            sS1[q*64 + l] = s1;
            sS2[q*64 + l] = s2;
        }
        __syncthreads();

        // ---------------- filter update (64 threads) ----------------
        if (tid < 64) {
            int l = tid;
            float s1 = sS1[l] + sS1[64+l] + sS1[128+l] + sS1[192+l];
            float s2 = sS2[l] + sS2[64+l] + sS2[128+l] + sS2[192+l];
            float mp = s1 * (1.0f/25.0f);
            float Pp = sQ[l] + s2 * (1.0f/25.0f) - mp*mp;
            float Jp = 1.0f / Pp;
            int  go  = (b*Tn + t)*Ln + l;
            float Kv = K_in[go];
            float kv = k_in[go];
            float Jf = Jp + Kv;
            float Pf = 1.0f / Jf;
            float mf = Pf * (Jp*mp + kv);
            out[ZF_SZ + 0*M_SZ + go] = mf;
            out[ZF_SZ + 1*M_SZ + go] = mp;
            out[ZF_SZ + 2*M_SZ + go] = Pf;
            out[ZF_SZ + 3*M_SZ + go] = Pp;
            sMf[l]  = mf;
            sSPf[l] = sqrtf(Pf);
        }
        __syncthreads();

        // ---------------- z update + z_f output ----------------
        for (int idx = tid; idx < Sn*Ln; idx += 256) {
            int s = idx >> 6, l = idx & 63;
            float w  = noise[((t*Sn + s)*Bn + b)*Ln + l];
            float zv = sMf[l] + sSPf[l] * w;
            sZ[s*ZS + l] = zv;
            out[((s*Bn + b)*Tn + t)*Ln + l] = zv;
        }
    }
}

extern "C" void kernel_launch(void* const* d_in, const int* in_sizes, int n_in,
                              void* d_out, int out_size)
{
    const float* k_in  = (const float*)d_in[0];
    const float* K_in  = (const float*)d_in[1];
    const float* noise = (const float*)d_in[2];
    const float* logQ  = (const float*)d_in[3];
    const float* m0    = (const float*)d_in[4];
    const float* logQ0 = (const float*)d_in[5];
    const float* W1    = (const float*)d_in[6];
    const float* b1    = (const float*)d_in[7];
    const float* W2    = (const float*)d_in[8];
    const float* b2    = (const float*)d_in[9];
    float* out = (float*)d_out;

    cudaFuncSetAttribute(nlf_kernel, cudaFuncAttributeMaxDynamicSharedMemorySize, SMEM_BYTES);
    nlf_kernel<<<Bn, 256, SMEM_BYTES>>>(k_in, K_in, noise, logQ, m0, logQ0,
                                        W1, b1, W2, b2, out);
}

// round 2
// speedup vs baseline: 1.4255x; 1.4255x over previous
#include <cuda_runtime.h>
#include <math.h>

#define Bn 128
#define Tn 256
#define Ln 64
#define Sn 25
#define Hn 128
#define NTHREADS 512

#define W1S 132   // stride (floats) for sW1 [64][132]
#define W2S 68    // stride for sW2 [128][68]
#define ZS  68    // stride for sZ/sPp/sMt [32][68]
#define THS 132   // stride for sTh [32][132]

#define ZF_SZ  52428800   // 25*128*256*64
#define M_SZ   2097152    // 128*256*64

// smem layout (floats)
#define OFF_W1  0
#define OFF_W2  (OFF_W1 + 64*W1S)
#define OFF_Z   (OFF_W2 + 128*W2S)
#define OFF_TH  (OFF_Z  + 32*ZS)
#define OFF_P   (OFF_TH + 32*THS)
#define OFF_MTH (OFF_P  + 32*ZS)
#define OFF_B1  (OFF_MTH+ 32*ZS)
#define OFF_B2  (OFF_B1 + 128)
#define OFF_Q   (OFF_B2 + 64)
#define OFF_MF  (OFF_Q  + 64)
#define OFF_SPF (OFF_MF + 64)
#define OFF_S1  (OFF_SPF+ 64)
#define OFF_S2  (OFF_S1 + 512)
#define SMEM_FLOATS (OFF_S2 + 512)
#define SMEM_BYTES (SMEM_FLOATS * 4)

typedef unsigned long long ull;

__device__ __forceinline__ float tanh_fast(float x) {
    float y;
    asm("tanh.approx.f32 %0, %1;" : "=f"(y) : "f"(x));
    return y;
}
__device__ __forceinline__ ull fma2(ull a, ull b, ull c) {
    ull d;
    asm("fma.rn.f32x2 %0, %1, %2, %3;" : "=l"(d) : "l"(a), "l"(b), "l"(c));
    return d;
}
__device__ __forceinline__ ull pack2(float lo, float hi) {
    ull d;
    asm("mov.b64 %0, {%1, %2};" : "=l"(d) : "f"(lo), "f"(hi));
    return d;
}
__device__ __forceinline__ float2 unpack2(ull v) {
    float2 r;
    asm("mov.b64 {%0, %1}, %2;" : "=f"(r.x), "=f"(r.y) : "l"(v));
    return r;
}

__global__ __launch_bounds__(NTHREADS, 1)
void nlf_kernel(const float* __restrict__ k_in,
                const float* __restrict__ K_in,
                const float* __restrict__ noise,
                const float* __restrict__ logQ,
                const float* __restrict__ m0,
                const float* __restrict__ logQ0,
                const float* __restrict__ W1,
                const float* __restrict__ b1,
                const float* __restrict__ W2,
                const float* __restrict__ b2,
                float* __restrict__ out)
{
    extern __shared__ float sm[];
    float* sW1 = sm + OFF_W1;   // [64][132]  W1[k][h]
    float* sW2 = sm + OFF_W2;   // [128][68]  W2[k][l]
    float* sZ  = sm + OFF_Z;    // [32][68]   z[s][l]   (rows 25..31 stay 0)
    float* sTh = sm + OFF_TH;   // [32][132]  tanh-out[s][h]
    float* sPp = sm + OFF_P;    // [32][68]   GEMM2 partial (k-half 1)
    float* sMt = sm + OFF_MTH;  // [32][68]   m_th[s][l]
    float* sB1 = sm + OFF_B1;
    float* sB2 = sm + OFF_B2;
    float* sQ  = sm + OFF_Q;
    float* sMf = sm + OFF_MF;
    float* sSPf= sm + OFF_SPF;
    float* sS1 = sm + OFF_S1;   // [8][64]
    float* sS2 = sm + OFF_S2;   // [8][64]

    const int tid  = threadIdx.x;
    const int b    = blockIdx.x;
    const int w    = tid >> 5;
    const int lane = tid & 31;

    // --- load weights / biases into smem, zero z buffer ---
    for (int i = tid; i < 64*128; i += NTHREADS) {
        int kk = i >> 7, h = i & 127;
        sW1[kk*W1S + h] = W1[i];
    }
    for (int i = tid; i < 128*64; i += NTHREADS) {
        int kk = i >> 6, l = i & 63;
        sW2[kk*W2S + l] = W2[i];
    }
    if (tid < 128) sB1[tid] = b1[tid];
    if (tid < 64)  sB2[tid] = b2[tid];
    for (int i = tid; i < 32*ZS; i += NTHREADS) sZ[i] = 0.0f;

    // --- t = 0 init (per-l, 64 threads) ---
    if (tid < 64) {
        int l = tid;
        float Qd = log1pf(expf(logQ[l]));
        sQ[l] = Qd;
        float P0 = log1pf(expf(logQ0[l]));
        float J0 = 1.0f / P0;
        float h0 = J0 * m0[l];
        int  go  = (b*Tn + 0)*Ln + l;
        float Kv = K_in[go];
        float kv = k_in[go];
        float Jf = J0 + Kv;
        float Pf = 1.0f / Jf;
        float mf = Pf * (h0 + kv);
        out[ZF_SZ + 0*M_SZ + go] = mf;
        out[ZF_SZ + 1*M_SZ + go] = m0[l];
        out[ZF_SZ + 2*M_SZ + go] = Pf;
        out[ZF_SZ + 3*M_SZ + go] = P0;
        sMf[l]  = mf;
        sSPf[l] = sqrtf(Pf);
    }
    __syncthreads();

    // --- z update for t = 0 ---
    for (int idx = tid; idx < Sn*Ln; idx += NTHREADS) {
        int s = idx >> 6, l = idx & 63;
        float wn = noise[((0*Sn + s)*Bn + b)*Ln + l];
        float zv = sMf[l] + sSPf[l] * wn;
        sZ[s*ZS + l] = zv;
        out[((s*Bn + b)*Tn + 0)*Ln + l] = zv;
    }

    // ---- GEMM1 mapping: 16 warps = 4 s-groups x 4 h-groups; lane = 4 sy x 8 hx
    const int g1_sb = (w >> 2) * 8;
    const int g1_hb = (w & 3) * 32;
    const int g1_hx = lane & 7;      // h = g1_hb + g1_hx*4 (4 consecutive)
    const int g1_sy = lane >> 3;     // s = g1_sb + g1_sy*2 + {0,1}
    const int g1_s0 = g1_sb + g1_sy*2;

    // ---- GEMM2 mapping: split-k halves of 8 warps; 4 s-groups x 2 l-groups
    const int g2_kh = w >> 3;        // 0/1 -> k in [kh*64, kh*64+64)
    const int w2    = w & 7;
    const int g2_sb = (w2 >> 1) * 8;
    const int g2_lb = (w2 & 1) * 32;
    const int g2_lx = lane & 7;      // l = g2_lb + g2_lx*4
    const int g2_sy = lane >> 3;
    const int g2_s0 = g2_sb + g2_sy*2;
    const int g2_l4 = g2_lb + g2_lx*4;

    for (int t = 1; t < Tn; t++) {
        // -------- prefetch global inputs for this step (overlap with GEMMs) ----
        float npf0, npf1, npf2, npf3;
        {
            int i0 = tid, i1 = tid + 512, i2 = tid + 1024, i3 = tid + 1536;
            npf0 = noise[((t*Sn + (i0>>6))*Bn + b)*Ln + (i0&63)];
            npf1 = noise[((t*Sn + (i1>>6))*Bn + b)*Ln + (i1&63)];
            npf2 = noise[((t*Sn + (i2>>6))*Bn + b)*Ln + (i2&63)];
            npf3 = (i3 < Sn*Ln) ? noise[((t*Sn + (i3>>6))*Bn + b)*Ln + (i3&63)] : 0.0f;
        }
        float kv_pf = 0.0f, Kv_pf = 0.0f;
        if (tid < 64) {
            int go = (b*Tn + t)*Ln + tid;
            Kv_pf = K_in[go];
            kv_pf = k_in[go];
        }

        __syncthreads();   // z for this step is ready

        // ---------------- GEMM1: th = tanh(z @ W1 + b1), [32 x 128] ------------
        {
            ull acc[2][2];
            {
                ulonglong2 bb = *(const ulonglong2*)&sB1[g1_hb + g1_hx*4];
                acc[0][0] = bb.x; acc[0][1] = bb.y;
                acc[1][0] = bb.x; acc[1][1] = bb.y;
            }
            #pragma unroll 4
            for (int k = 0; k < 64; k += 4) {
                float4 z0 = *(const float4*)&sZ[(g1_s0 + 0)*ZS + k];
                float4 z1 = *(const float4*)&sZ[(g1_s0 + 1)*ZS + k];
                float za0[4] = {z0.x, z0.y, z0.z, z0.w};
                float za1[4] = {z1.x, z1.y, z1.z, z1.w};
                #pragma unroll
                for (int j = 0; j < 4; j++) {
                    ulonglong2 wv = *(const ulonglong2*)&sW1[(k+j)*W1S + g1_hb + g1_hx*4];
                    ull zd0 = pack2(za0[j], za0[j]);
                    ull zd1 = pack2(za1[j], za1[j]);
                    acc[0][0] = fma2(zd0, wv.x, acc[0][0]);
                    acc[0][1] = fma2(zd0, wv.y, acc[0][1]);
                    acc[1][0] = fma2(zd1, wv.x, acc[1][0]);
                    acc[1][1] = fma2(zd1, wv.y, acc[1][1]);
                }
            }
            #pragma unroll
            for (int i = 0; i < 2; i++) {
                float2 a0 = unpack2(acc[i][0]);
                float2 a1 = unpack2(acc[i][1]);
                float4 rr;
                rr.x = tanh_fast(a0.x);
                rr.y = tanh_fast(a0.y);
                rr.z = tanh_fast(a1.x);
                rr.w = tanh_fast(a1.y);
                *(float4*)&sTh[(g1_s0 + i)*THS + g1_hb + g1_hx*4] = rr;
            }
        }
        __syncthreads();

        // ---------------- GEMM2: m_th = z + th @ W2 + b2, [32 x 64], split-k ---
        {
            ull acc[2][2];
            acc[0][0] = 0ULL; acc[0][1] = 0ULL;
            acc[1][0] = 0ULL; acc[1][1] = 0ULL;

            const int k0 = g2_kh * 64;
            #pragma unroll 4
            for (int kk = 0; kk < 64; kk += 4) {
                int k = k0 + kk;
                float4 t0 = *(const float4*)&sTh[(g2_s0 + 0)*THS + k];
                float4 t1 = *(const float4*)&sTh[(g2_s0 + 1)*THS + k];
                float ta0[4] = {t0.x, t0.y, t0.z, t0.w};
                float ta1[4] = {t1.x, t1.y, t1.z, t1.w};
                #pragma unroll
                for (int j = 0; j < 4; j++) {
                    ulonglong2 wv = *(const ulonglong2*)&sW2[(k+j)*W2S + g2_l4];
                    ull td0 = pack2(ta0[j], ta0[j]);
                    ull td1 = pack2(ta1[j], ta1[j]);
                    acc[0][0] = fma2(td0, wv.x, acc[0][0]);
                    acc[0][1] = fma2(td0, wv.y, acc[0][1]);
                    acc[1][0] = fma2(td1, wv.x, acc[1][0]);
                    acc[1][1] = fma2(td1, wv.y, acc[1][1]);
                }
            }
            if (g2_kh == 1) {
                #pragma unroll
                for (int i = 0; i < 2; i++) {
                    float2 a0 = unpack2(acc[i][0]);
                    float2 a1 = unpack2(acc[i][1]);
                    *(float4*)&sPp[(g2_s0 + i)*ZS + g2_l4] =
                        make_float4(a0.x, a0.y, a1.x, a1.y);
                }
            }
            __syncthreads();
            if (g2_kh == 0) {
                float4 b4 = *(const float4*)&sB2[g2_l4];
                #pragma unroll
                for (int i = 0; i < 2; i++) {
                    int s = g2_s0 + i;
                    float4 p  = *(const float4*)&sPp[s*ZS + g2_l4];
                    float4 z4 = *(const float4*)&sZ[s*ZS + g2_l4];
                    float2 a0 = unpack2(acc[i][0]);
                    float2 a1 = unpack2(acc[i][1]);
                    float4 m;
                    m.x = a0.x + p.x + b4.x + z4.x;
                    m.y = a0.y + p.y + b4.y + z4.y;
                    m.z = a1.x + p.z + b4.z + z4.z;
                    m.w = a1.y + p.w + b4.w + z4.w;
                    *(float4*)&sMt[s*ZS + g2_l4] = m;
                }
            }
        }
        __syncthreads();

        // ---------------- moment partial reduction over s (8 groups of 4) ------
        {
            int l = tid & 63, q = tid >> 6;
            float s1 = 0.0f, s2 = 0.0f;
            #pragma unroll
            for (int i = 0; i < 4; i++) {
                int s = q*4 + i;
                if (s < Sn) {
                    float v = sMt[s*ZS + l];
                    s1 += v;
                    s2 = fmaf(v, v, s2);
                }
            }
            sS1[q*64 + l] = s1;
            sS2[q*64 + l] = s2;
        }
        __syncthreads();

        // ---------------- filter update (64 threads) ---------------------------
        if (tid < 64) {
            int l = tid;
            float s1 = 0.0f, s2 = 0.0f;
            #pragma unroll
            for (int q = 0; q < 8; q++) {
                s1 += sS1[q*64 + l];
                s2 += sS2[q*64 + l];
            }
            float mp = s1 * (1.0f/25.0f);
            float Pp = sQ[l] + s2 * (1.0f/25.0f) - mp*mp;
            float Jp = 1.0f / Pp;
            float Jf = Jp + Kv_pf;
            float Pf = 1.0f / Jf;
            float mf = Pf * (Jp*mp + kv_pf);
            int  go  = (b*Tn + t)*Ln + l;
            out[ZF_SZ + 0*M_SZ + go] = mf;
            out[ZF_SZ + 1*M_SZ + go] = mp;
            out[ZF_SZ + 2*M_SZ + go] = Pf;
            out[ZF_SZ + 3*M_SZ + go] = Pp;
            sMf[l]  = mf;
            sSPf[l] = sqrtf(Pf);
        }
        __syncthreads();

        // ---------------- z update + z_f output (uses prefetched noise) --------
        {
            int i0 = tid, i1 = tid + 512, i2 = tid + 1024, i3 = tid + 1536;
            {
                int s = i0 >> 6, l = i0 & 63;
                float zv = sMf[l] + sSPf[l] * npf0;
                sZ[s*ZS + l] = zv;
                out[((s*Bn + b)*Tn + t)*Ln + l] = zv;
            }
            {
                int s = i1 >> 6, l = i1 & 63;
                float zv = sMf[l] + sSPf[l] * npf1;
                sZ[s*ZS + l] = zv;
                out[((s*Bn + b)*Tn + t)*Ln + l] = zv;
            }
            {
                int s = i2 >> 6, l = i2 & 63;
                float zv = sMf[l] + sSPf[l] * npf2;
                sZ[s*ZS + l] = zv;
                out[((s*Bn + b)*Tn + t)*Ln + l] = zv;
            }
            if (i3 < Sn*Ln) {
                int s = i3 >> 6, l = i3 & 63;
                float zv = sMf[l] + sSPf[l] * npf3;
                sZ[s*ZS + l] = zv;
                out[((s*Bn + b)*Tn + t)*Ln + l] = zv;
            }
        }
    }
}

extern "C" void kernel_launch(void* const* d_in, const int* in_sizes, int n_in,
                              void* d_out, int out_size)
{
    const float* k_in  = (const float*)d_in[0];
    const float* K_in  = (const float*)d_in[1];
    const float* noise = (const float*)d_in[2];
    const float* logQ  = (const float*)d_in[3];
    const float* m0    = (const float*)d_in[4];
    const float* logQ0 = (const float*)d_in[5];
    const float* W1    = (const float*)d_in[6];
    const float* b1    = (const float*)d_in[7];
    const float* W2    = (const float*)d_in[8];
    const float* b2    = (const float*)d_in[9];
    float* out = (float*)d_out;

    cudaFuncSetAttribute(nlf_kernel, cudaFuncAttributeMaxDynamicSharedMemorySize, SMEM_BYTES);
    nlf_kernel<<<Bn, NTHREADS, SMEM_BYTES>>>(k_in, K_in, noise, logQ, m0, logQ0,
                                             W1, b1, W2, b2, out);
}

// round 4
// speedup vs baseline: 1.9796x; 1.3887x over previous
#include <cuda_runtime.h>
#include <math.h>

#define Bn 128
#define Tn 256
#define Ln 64
#define Sn 25
#define Hn 128
#define NT 256

#define ZS  68
#define THS 132

#define ZF_SZ  52428800   // 25*128*256*64
#define M_SZ   2097152    // 128*256*64

// smem layout (floats)
#define OFF_Z   0
#define OFF_TH  (OFF_Z + 32*ZS)
#define OFF_MTH (OFF_TH + 32*THS)
#define OFF_Q   (OFF_MTH + 32*ZS)
#define OFF_MF  (OFF_Q + 64)
#define OFF_SPF (OFF_MF + 64)
#define OFF_S1  (OFF_SPF + 64)
#define OFF_S2  (OFF_S1 + 256)
#define SMEM_FLOATS (OFF_S2 + 256)
#define SMEM_BYTES (SMEM_FLOATS * 4)

typedef unsigned long long ull;

__device__ __forceinline__ float tanh_fast(float x) {
    float y;
    asm("tanh.approx.f32 %0, %1;" : "=f"(y) : "f"(x));
    return y;
}
__device__ __forceinline__ ull fma2(ull a, ull b, ull c) {
    ull d;
    asm("fma.rn.f32x2 %0, %1, %2, %3;" : "=l"(d) : "l"(a), "l"(b), "l"(c));
    return d;
}
__device__ __forceinline__ ull fadd2(ull a, ull b) {
    ull d;
    asm("add.rn.f32x2 %0, %1, %2;" : "=l"(d) : "l"(a), "l"(b));
    return d;
}
__device__ __forceinline__ ull pack2(float lo, float hi) {
    ull d;
    asm("mov.b64 %0, {%1, %2};" : "=l"(d) : "f"(lo), "f"(hi));
    return d;
}
__device__ __forceinline__ float2 unpack2(ull v) {
    float2 r;
    asm("mov.b64 {%0, %1}, %2;" : "=f"(r.x), "=f"(r.y) : "l"(v));
    return r;
}
__device__ __forceinline__ ull shfl_xor_ull(ull v, int m) {
    unsigned lo = (unsigned)v, hi = (unsigned)(v >> 32);
    lo = __shfl_xor_sync(0xffffffffu, lo, m);
    hi = __shfl_xor_sync(0xffffffffu, hi, m);
    return ((ull)hi << 32) | (ull)lo;
}

__global__ __launch_bounds__(NT, 1)
void nlf_kernel(const float* __restrict__ k_in,
                const float* __restrict__ K_in,
                const float* __restrict__ noise,
                const float* __restrict__ logQ,
                const float* __restrict__ m0,
                const float* __restrict__ logQ0,
                const float* __restrict__ W1,
                const float* __restrict__ b1,
                const float* __restrict__ W2,
                const float* __restrict__ b2,
                float* __restrict__ out)
{
    extern __shared__ float sm[];
    float* sZ  = sm + OFF_Z;    // [32][68] z[s][l]  (rows 28..31 stay 0)
    float* sTh = sm + OFF_TH;   // [32][132] tanh-out[s][h]
    float* sMt = sm + OFF_MTH;  // [32][68] m_th[s][l]
    float* sQ  = sm + OFF_Q;
    float* sMf = sm + OFF_MF;
    float* sSPf= sm + OFF_SPF;
    float* sS1 = sm + OFF_S1;   // [4][64]
    float* sS2 = sm + OFF_S2;   // [4][64]

    const int tid  = threadIdx.x;
    const int b    = blockIdx.x;
    const int w    = tid >> 5;
    const int lane = tid & 31;

    // -------- thread mappings --------
    // warps: hcl = w>>1 (cluster for h / l), sgrp = w&1 (s halves)
    const int hcl  = w >> 1;
    const int sgrp = w & 1;
    const int nsub = 4 - sgrp;          // sgrp0: s 0..15 (4 sub), sgrp1: s 16..27 (3 sub)

    // GEMM1: lane = hs(2b) | kg1(3b)<<2 ; thread tile 8h x 8k
    const int hs  = lane & 3;
    const int kg1 = lane >> 2;          // 0..7
    const int H8  = (hcl*4 + hs) * 8;   // 8 h values
    const int K1  = kg1 * 8;            // 8 k values

    // GEMM2: lane = lgs(1b) | kg2(4b)<<1 ; thread tile 8l x 8k
    const int lgs = lane & 1;
    const int kg2 = lane >> 1;          // 0..15
    const int L8  = (hcl*2 + lgs) * 8;  // 8 l values
    const int K2  = kg2 * 8;            // 8 k values

    // -------- register-resident weights --------
    ull w1r[8][4];
    #pragma unroll
    for (int kk = 0; kk < 8; kk++) {
        const float* p = W1 + (K1 + kk)*Hn + H8;
        float4 a = *(const float4*)p;
        float4 c = *(const float4*)(p + 4);
        w1r[kk][0] = pack2(a.x, a.y);
        w1r[kk][1] = pack2(a.z, a.w);
        w1r[kk][2] = pack2(c.x, c.y);
        w1r[kk][3] = pack2(c.z, c.w);
    }
    ull w2r[8][4];
    #pragma unroll
    for (int kk = 0; kk < 8; kk++) {
        const float* p = W2 + (K2 + kk)*Ln + L8;
        float4 a = *(const float4*)p;
        float4 c = *(const float4*)(p + 4);
        w2r[kk][0] = pack2(a.x, a.y);
        w2r[kk][1] = pack2(a.z, a.w);
        w2r[kk][2] = pack2(c.x, c.y);
        w2r[kk][3] = pack2(c.z, c.w);
    }
    // per-thread final-output biases
    const int hh_f = H8 + (kg1 & 1)*4;          // GEMM1 final h base (4 floats)
    const float4 b1f = *(const float4*)&b1[hh_f];
    const int ll_f = L8 + 2*(kg2 & 3);          // GEMM2 final l base (2 floats)
    const ull b2p = pack2(b2[ll_f], b2[ll_f + 1]);

    // -------- init: zero z, t=0 filter --------
    for (int i = tid; i < 32*ZS; i += NT) sZ[i] = 0.0f;
    if (tid < 64) {
        int l = tid;
        float Qd = log1pf(expf(logQ[l]));
        sQ[l] = Qd;
        float P0 = log1pf(expf(logQ0[l]));
        float J0 = 1.0f / P0;
        float h0 = J0 * m0[l];
        int  go  = (b*Tn + 0)*Ln + l;
        float Kv = K_in[go];
        float kv = k_in[go];
        float Jf = J0 + Kv;
        float Pf = 1.0f / Jf;
        float mf = Pf * (h0 + kv);
        out[ZF_SZ + 0*M_SZ + go] = mf;
        out[ZF_SZ + 1*M_SZ + go] = m0[l];
        out[ZF_SZ + 2*M_SZ + go] = Pf;
        out[ZF_SZ + 3*M_SZ + go] = P0;
        sMf[l]  = mf;
        sSPf[l] = sqrtf(Pf);
    }
    __syncthreads();

    // z update for t = 0
    #pragma unroll
    for (int i = 0; i < 6; i++) {
        int idx = tid + i*NT;
        int s = idx >> 6, l = idx & 63;
        float wn = noise[((0*Sn + s)*Bn + b)*Ln + l];
        float zv = sMf[l] + sSPf[l] * wn;
        sZ[s*ZS + l] = zv;
        out[((s*Bn + b)*Tn + 0)*Ln + l] = zv;
    }
    if (tid < 64) {
        float wn = noise[((0*Sn + 24)*Bn + b)*Ln + tid];
        float zv = sMf[tid] + sSPf[tid] * wn;
        sZ[24*ZS + tid] = zv;
        out[((24*Bn + b)*Tn + 0)*Ln + tid] = zv;
    }

    for (int t = 1; t < Tn; t++) {
        // -------- prefetch globals (overlap with GEMMs) --------
        float npf[7];
        #pragma unroll
        for (int i = 0; i < 6; i++) {
            int idx = tid + i*NT;
            npf[i] = noise[((t*Sn + (idx >> 6))*Bn + b)*Ln + (idx & 63)];
        }
        npf[6] = (tid < 64) ? noise[((t*Sn + 24)*Bn + b)*Ln + tid] : 0.0f;
        float kv_pf = 0.0f, Kv_pf = 0.0f;
        if (tid < 64) {
            int go = (b*Tn + t)*Ln + tid;
            Kv_pf = K_in[go];
            kv_pf = k_in[go];
        }

        __syncthreads();   // z for this step ready

        // ============ GEMM1: th = tanh(z @ W1 + b1) ============
        for (int sp = 0; sp < nsub; sp++) {
            const int s0 = sgrp*16 + sp*4;
            float4 zc[4][2];
            #pragma unroll
            for (int si = 0; si < 4; si++) {
                zc[si][0] = *(const float4*)&sZ[(s0+si)*ZS + K1];
                zc[si][1] = *(const float4*)&sZ[(s0+si)*ZS + K1 + 4];
            }
            ull A[16];
            #pragma unroll
            for (int i = 0; i < 16; i++) A[i] = 0ULL;
            #pragma unroll
            for (int c = 0; c < 2; c++) {
                #pragma unroll
                for (int q = 0; q < 4; q++) {
                    const int kk = c*4 + q;
                    #pragma unroll
                    for (int si = 0; si < 4; si++) {
                        float zv = (q==0) ? zc[si][c].x : (q==1) ? zc[si][c].y
                                 : (q==2) ? zc[si][c].z : zc[si][c].w;
                        ull zd = pack2(zv, zv);
                        #pragma unroll
                        for (int j = 0; j < 4; j++)
                            A[si*4+j] = fma2(zd, w1r[kk][j], A[si*4+j]);
                    }
                }
            }
            // reduce-scatter over kg1 (masks 16,8,4): 16 -> 2 ull
            #pragma unroll
            for (int r = 0; r < 3; r++) {
                const int m    = 16 >> r;
                const int half = 8 >> r;          // 8,4,2
                const bool hi  = (lane & m) != 0;
                #pragma unroll
                for (int i = 0; i < half; i++) {
                    ull sendv = hi ? A[i] : A[half+i];
                    ull recv  = shfl_xor_ull(sendv, m);
                    ull keep  = hi ? A[half+i] : A[i];
                    A[i] = fadd2(keep, recv);
                }
            }
            // lane holds (s = s0 + kg1>>1, h = hh_f..hh_f+4)
            const int sf = s0 + (kg1 >> 1);
            float2 u0 = unpack2(A[0]);
            float2 u1 = unpack2(A[1]);
            float4 r;
            r.x = tanh_fast(u0.x + b1f.x);
            r.y = tanh_fast(u0.y + b1f.y);
            r.z = tanh_fast(u1.x + b1f.z);
            r.w = tanh_fast(u1.y + b1f.w);
            *(float4*)&sTh[sf*THS + hh_f] = r;
        }
        __syncthreads();

        // ============ GEMM2: m_th = z + th @ W2 + b2 ============
        for (int sp = 0; sp < nsub; sp++) {
            const int s0 = sgrp*16 + sp*4;
            float4 tc[4][2];
            #pragma unroll
            for (int si = 0; si < 4; si++) {
                tc[si][0] = *(const float4*)&sTh[(s0+si)*THS + K2];
                tc[si][1] = *(const float4*)&sTh[(s0+si)*THS + K2 + 4];
            }
            ull A[16];
            #pragma unroll
            for (int i = 0; i < 16; i++) A[i] = 0ULL;
            #pragma unroll
            for (int c = 0; c < 2; c++) {
                #pragma unroll
                for (int q = 0; q < 4; q++) {
                    const int kk = c*4 + q;
                    #pragma unroll
                    for (int si = 0; si < 4; si++) {
                        float tv = (q==0) ? tc[si][c].x : (q==1) ? tc[si][c].y
                                 : (q==2) ? tc[si][c].z : tc[si][c].w;
                        ull td = pack2(tv, tv);
                        #pragma unroll
                        for (int j = 0; j < 4; j++)
                            A[si*4+j] = fma2(td, w2r[kk][j], A[si*4+j]);
                    }
                }
            }
            // reduce-scatter over kg2 (masks 16,8,4,2): 16 -> 1 ull
            #pragma unroll
            for (int r = 0; r < 4; r++) {
                const int m    = 16 >> r;
                const int half = 8 >> r;          // 8,4,2,1
                const bool hi  = (lane & m) != 0;
                #pragma unroll
                for (int i = 0; i < half; i++) {
                    ull sendv = hi ? A[i] : A[half+i];
                    ull recv  = shfl_xor_ull(sendv, m);
                    ull keep  = hi ? A[half+i] : A[i];
                    A[i] = fadd2(keep, recv);
                }
            }
            // lane holds (s = s0 + kg2>>2, l = ll_f, ll_f+1)
            const int sf = s0 + (kg2 >> 2);
            ull zp = *(const ull*)&sZ[sf*ZS + ll_f];
            ull mm = fadd2(fadd2(A[0], b2p), zp);
            *(ull*)&sMt[sf*ZS + ll_f] = mm;
        }
        __syncthreads();

        // -------- moment partial reduction over s --------
        {
            int l = tid & 63, q = tid >> 6;       // q in 0..3
            float s1 = 0.0f, s2 = 0.0f;
            #pragma unroll
            for (int i = 0; i < 8; i++) {
                int s = q*8 + i;
                if (s < Sn) {
                    float v = sMt[s*ZS + l];
                    s1 += v;
                    s2 = fmaf(v, v, s2);
                }
            }
            sS1[q*64 + l] = s1;
            sS2[q*64 + l] = s2;
        }
        __syncthreads();

        // -------- filter update (64 threads) --------
        if (tid < 64) {
            int l = tid;
            float s1 = sS1[l] + sS1[64+l] + sS1[128+l] + sS1[192+l];
            float s2 = sS2[l] + sS2[64+l] + sS2[128+l] + sS2[192+l];
            float mp = s1 * (1.0f/25.0f);
            float Pp = sQ[l] + s2 * (1.0f/25.0f) - mp*mp;
            float Jp = 1.0f / Pp;
            float Jf = Jp + Kv_pf;
            float Pf = 1.0f / Jf;
            float mf = Pf * (Jp*mp + kv_pf);
            int  go  = (b*Tn + t)*Ln + l;
            out[ZF_SZ + 0*M_SZ + go] = mf;
            out[ZF_SZ + 1*M_SZ + go] = mp;
            out[ZF_SZ + 2*M_SZ + go] = Pf;
            out[ZF_SZ + 3*M_SZ + go] = Pp;
            sMf[l]  = mf;
            sSPf[l] = sqrtf(Pf);
        }
        __syncthreads();

        // -------- z update + z_f output --------
        #pragma unroll
        for (int i = 0; i < 6; i++) {
            int idx = tid + i*NT;
            int s = idx >> 6, l = idx & 63;
            float zv = sMf[l] + sSPf[l] * npf[i];
            sZ[s*ZS + l] = zv;
            out[((s*Bn + b)*Tn + t)*Ln + l] = zv;
        }
        if (tid < 64) {
            float zv = sMf[tid] + sSPf[tid] * npf[6];
            sZ[24*ZS + tid] = zv;
            out[((24*Bn + b)*Tn + t)*Ln + tid] = zv;
        }
    }
}

extern "C" void kernel_launch(void* const* d_in, const int* in_sizes, int n_in,
                              void* d_out, int out_size)
{
    const float* k_in  = (const float*)d_in[0];
    const float* K_in  = (const float*)d_in[1];
    const float* noise = (const float*)d_in[2];
    const float* logQ  = (const float*)d_in[3];
    const float* m0    = (const float*)d_in[4];
    const float* logQ0 = (const float*)d_in[5];
    const float* W1    = (const float*)d_in[6];
    const float* b1    = (const float*)d_in[7];
    const float* W2    = (const float*)d_in[8];
    const float* b2    = (const float*)d_in[9];
    float* out = (float*)d_out;

    cudaFuncSetAttribute(nlf_kernel, cudaFuncAttributeMaxDynamicSharedMemorySize, SMEM_BYTES);
    nlf_kernel<<<Bn, NT, SMEM_BYTES>>>(k_in, K_in, noise, logQ, m0, logQ0,
                                       W1, b1, W2, b2, out);
}

// round 6
// speedup vs baseline: 1.9807x; 1.0005x over previous
#include <cuda_runtime.h>
#include <math.h>

#define Bn 128
#define Tn 256
#define Ln 64
#define Sn 25
#define Hn 128
#define NT 256

#define ZS  68
#define THS 132

#define ZF_SZ  52428800   // 25*128*256*64
#define M_SZ   2097152    // 128*256*64

// smem layout (floats)
#define OFF_Z   0
#define OFF_TH  (OFF_Z + 32*ZS)
#define OFF_P1  (OFF_TH + 32*THS)
#define OFF_P2  (OFF_P1 + 128)
#define SMEM_FLOATS (OFF_P2 + 128)
#define SMEM_BYTES (SMEM_FLOATS * 4)

typedef unsigned long long ull;

__device__ __forceinline__ float tanh_fast(float x) {
    float y;
    asm("tanh.approx.f32 %0, %1;" : "=f"(y) : "f"(x));
    return y;
}
__device__ __forceinline__ ull fma2(ull a, ull b, ull c) {
    ull d;
    asm("fma.rn.f32x2 %0, %1, %2, %3;" : "=l"(d) : "l"(a), "l"(b), "l"(c));
    return d;
}
__device__ __forceinline__ ull fadd2(ull a, ull b) {
    ull d;
    asm("add.rn.f32x2 %0, %1, %2;" : "=l"(d) : "l"(a), "l"(b));
    return d;
}
__device__ __forceinline__ ull pack2(float lo, float hi) {
    ull d;
    asm("mov.b64 %0, {%1, %2};" : "=l"(d) : "f"(lo), "f"(hi));
    return d;
}
__device__ __forceinline__ float2 unpack2(ull v) {
    float2 r;
    asm("mov.b64 {%0, %1}, %2;" : "=f"(r.x), "=f"(r.y) : "l"(v));
    return r;
}
__device__ __forceinline__ ull shfl_xor_ull(ull v, int m) {
    unsigned lo = (unsigned)v, hi = (unsigned)(v >> 32);
    lo = __shfl_xor_sync(0xffffffffu, lo, m);
    hi = __shfl_xor_sync(0xffffffffu, hi, m);
    return ((ull)hi << 32) | (ull)lo;
}

// ---------------- GEMM1 sub-pass (4 rows starting at s0_) ----------------
#define G1_PASS(s0_) do {                                                     \
    float4 zc[4][2];                                                          \
    _Pragma("unroll")                                                         \
    for (int si = 0; si < 4; si++) {                                          \
        zc[si][0] = *(const float4*)&sZ[((s0_)+si)*ZS + K1];                  \
        zc[si][1] = *(const float4*)&sZ[((s0_)+si)*ZS + K1 + 4];              \
    }                                                                         \
    ull A[16];                                                                \
    _Pragma("unroll")                                                         \
    for (int i = 0; i < 16; i++) A[i] = 0ULL;                                 \
    _Pragma("unroll")                                                         \
    for (int c = 0; c < 2; c++) {                                             \
        _Pragma("unroll")                                                     \
        for (int q = 0; q < 4; q++) {                                         \
            const int kk = c*4 + q;                                           \
            _Pragma("unroll")                                                 \
            for (int si = 0; si < 4; si++) {                                  \
                float zv = (q==0) ? zc[si][c].x : (q==1) ? zc[si][c].y        \
                         : (q==2) ? zc[si][c].z : zc[si][c].w;                \
                ull zd = pack2(zv, zv);                                       \
                _Pragma("unroll")                                             \
                for (int j = 0; j < 4; j++)                                   \
                    A[si*4+j] = fma2(zd, w1r[kk][j], A[si*4+j]);              \
            }                                                                 \
        }                                                                     \
    }                                                                         \
    _Pragma("unroll")                                                         \
    for (int r = 0; r < 3; r++) {                                             \
        const int m    = 16 >> r;                                             \
        const int half = 8 >> r;                                              \
        const bool hi  = (lane & m) != 0;                                     \
        _Pragma("unroll")                                                     \
        for (int i = 0; i < half; i++) {                                      \
            ull sendv = hi ? A[i] : A[half+i];                                \
            ull recv  = shfl_xor_ull(sendv, m);                               \
            ull keep  = hi ? A[half+i] : A[i];                                \
            A[i] = fadd2(keep, recv);                                         \
        }                                                                     \
    }                                                                         \
    const int sf = (s0_) + (kg1 >> 1);                                        \
    float2 u0 = unpack2(A[0]);                                                \
    float2 u1 = unpack2(A[1]);                                                \
    float4 r4;                                                                \
    r4.x = tanh_fast(u0.x + b1f.x);                                           \
    r4.y = tanh_fast(u0.y + b1f.y);                                           \
    r4.z = tanh_fast(u1.x + b1f.z);                                           \
    r4.w = tanh_fast(u1.y + b1f.w);                                           \
    *(float4*)&sTh[sf*THS + hh_f] = r4;                                       \
} while (0)

// ---------------- GEMM2 sub-pass + moment accumulate ----------------
#define G2_PASS(s0_) do {                                                     \
    float4 tc[4][2];                                                          \
    _Pragma("unroll")                                                         \
    for (int si = 0; si < 4; si++) {                                          \
        tc[si][0] = *(const float4*)&sTh[((s0_)+si)*THS + K2];                \
        tc[si][1] = *(const float4*)&sTh[((s0_)+si)*THS + K2 + 4];            \
    }                                                                         \
    ull A[16];                                                                \
    _Pragma("unroll")                                                         \
    for (int i = 0; i < 16; i++) A[i] = 0ULL;                                 \
    _Pragma("unroll")                                                         \
    for (int c = 0; c < 2; c++) {                                             \
        _Pragma("unroll")                                                     \
        for (int q = 0; q < 4; q++) {                                         \
            const int kk = c*4 + q;                                           \
            _Pragma("unroll")                                                 \
            for (int si = 0; si < 4; si++) {                                  \
                float tv = (q==0) ? tc[si][c].x : (q==1) ? tc[si][c].y        \
                         : (q==2) ? tc[si][c].z : tc[si][c].w;                \
                ull td = pack2(tv, tv);                                       \
                _Pragma("unroll")                                             \
                for (int j = 0; j < 4; j++)                                   \
                    A[si*4+j] = fma2(td, w2r[kk][j], A[si*4+j]);              \
            }                                                                 \
        }                                                                     \
    }                                                                         \
    _Pragma("unroll")                                                         \
    for (int r = 0; r < 4; r++) {                                             \
        const int m    = 16 >> r;                                             \
        const int half = 8 >> r;                                              \
        const bool hi  = (lane & m) != 0;                                     \
        _Pragma("unroll")                                                     \
        for (int i = 0; i < half; i++) {                                      \
            ull sendv = hi ? A[i] : A[half+i];                                \
            ull recv  = shfl_xor_ull(sendv, m);                               \
            ull keep  = hi ? A[half+i] : A[i];                                \
            A[i] = fadd2(keep, recv);                                         \
        }                                                                     \
    }                                                                         \
    const int sf = (s0_) + (kg2 >> 2);                                        \
    ull zp = *(const ull*)&sZ[sf*ZS + ll_f];                                  \
    ull mm = fadd2(fadd2(A[0], b2p), zp);                                     \
    if ((s0_) == 24 && sf >= Sn) mm = 0ULL;                                   \
    s1a = fadd2(s1a, mm);                                                     \
    s2a = fma2(mm, mm, s2a);                                                  \
} while (0)

__global__ __launch_bounds__(NT, 1)
void nlf_kernel(const float* __restrict__ k_in,
                const float* __restrict__ K_in,
                const float* __restrict__ noise,
                const float* __restrict__ logQ,
                const float* __restrict__ m0,
                const float* __restrict__ logQ0,
                const float* __restrict__ W1,
                const float* __restrict__ b1,
                const float* __restrict__ W2,
                const float* __restrict__ b2,
                float* __restrict__ out)
{
    extern __shared__ float sm[];
    float* sZ  = sm + OFF_Z;    // [32][68]  z[s][l]  (rows 25..31 stay 0)
    float* sTh = sm + OFF_TH;   // [32][132] tanh-out[s][h]
    float* sP1 = sm + OFF_P1;   // [2][64]   per-sgrp moment partial sum
    float* sP2 = sm + OFF_P2;   // [2][64]   per-sgrp moment partial sumsq

    const int tid  = threadIdx.x;
    const int b    = blockIdx.x;
    const int w    = tid >> 5;
    const int lane = tid & 31;
    const int lq   = tid & 63;   // this thread's filter l

    const int hcl  = w >> 1;
    const int sgrp = w & 1;

    // GEMM1 mapping
    const int hs  = lane & 3;
    const int kg1 = lane >> 2;
    const int H8  = (hcl*4 + hs) * 8;
    const int K1  = kg1 * 8;
    // GEMM2 mapping
    const int lgs = lane & 1;
    const int kg2 = lane >> 1;
    const int L8  = (hcl*2 + lgs) * 8;
    const int K2  = kg2 * 8;

    // -------- register-resident weights --------
    ull w1r[8][4];
    #pragma unroll
    for (int kk = 0; kk < 8; kk++) {
        const float* p = W1 + (K1 + kk)*Hn + H8;
        float4 a = *(const float4*)p;
        float4 c = *(const float4*)(p + 4);
        w1r[kk][0] = pack2(a.x, a.y);
        w1r[kk][1] = pack2(a.z, a.w);
        w1r[kk][2] = pack2(c.x, c.y);
        w1r[kk][3] = pack2(c.z, c.w);
    }
    ull w2r[8][4];
    #pragma unroll
    for (int kk = 0; kk < 8; kk++) {
        const float* p = W2 + (K2 + kk)*Ln + L8;
        float4 a = *(const float4*)p;
        float4 c = *(const float4*)(p + 4);
        w2r[kk][0] = pack2(a.x, a.y);
        w2r[kk][1] = pack2(a.z, a.w);
        w2r[kk][2] = pack2(c.x, c.y);
        w2r[kk][3] = pack2(c.z, c.w);
    }
    const int hh_f = H8 + (kg1 & 1)*4;
    const float4 b1f = *(const float4*)&b1[hh_f];
    const int ll_f = L8 + 2*(kg2 & 3);
    const ull b2p = pack2(b2[ll_f], b2[ll_f + 1]);

    // per-thread softplus(log_Q) for its l
    const float Qd = log1pf(expf(logQ[lq]));

    // -------- init: zero z, t=0 filter --------
    for (int i = tid; i < 32*ZS; i += NT) sZ[i] = 0.0f;
    if (tid < 64) {
        int l = tid;
        float P0 = log1pf(expf(logQ0[l]));
        float J0 = 1.0f / P0;
        float h0 = J0 * m0[l];
        int  go  = (b*Tn + 0)*Ln + l;
        float Kv = K_in[go];
        float kv = k_in[go];
        float Jf = J0 + Kv;
        float Pf = 1.0f / Jf;
        float mf = Pf * (h0 + kv);
        out[ZF_SZ + 0*M_SZ + go] = mf;
        out[ZF_SZ + 1*M_SZ + go] = m0[l];
        out[ZF_SZ + 2*M_SZ + go] = Pf;
        out[ZF_SZ + 3*M_SZ + go] = P0;
        sP1[l] = mf;
        sP2[l] = sqrtf(Pf);
    }
    __syncthreads();

    // z update for t = 0
    {
        float mf = sP1[lq], spf = sP2[lq];
        #pragma unroll
        for (int i = 0; i < 6; i++) {
            int idx = tid + i*NT;
            int s = idx >> 6;
            float wn = noise[((0*Sn + s)*Bn + b)*Ln + lq];
            float zv = mf + spf * wn;
            sZ[s*ZS + lq] = zv;
            out[((s*Bn + b)*Tn + 0)*Ln + lq] = zv;
        }
        if (tid < 64) {
            float wn = noise[((0*Sn + 24)*Bn + b)*Ln + lq];
            float zv = mf + spf * wn;
            sZ[24*ZS + lq] = zv;
            out[((24*Bn + b)*Tn + 0)*Ln + lq] = zv;
        }
    }

    for (int t = 1; t < Tn; t++) {
        // -------- prefetch globals (overlap with GEMMs) --------
        float npf[7];
        #pragma unroll
        for (int i = 0; i < 6; i++) {
            int idx = tid + i*NT;
            npf[i] = noise[((t*Sn + (idx >> 6))*Bn + b)*Ln + lq];
        }
        npf[6] = (tid < 64) ? noise[((t*Sn + 24)*Bn + b)*Ln + lq] : 0.0f;
        const int go = (b*Tn + t)*Ln + lq;
        float Kv_pf = K_in[go];
        float kv_pf = k_in[go];

        __syncthreads();   // z for this step ready

        // ============ GEMM1: th = tanh(z @ W1 + b1) ============
        if (sgrp == 0) {
            G1_PASS(0); G1_PASS(4); G1_PASS(8); G1_PASS(12);
        } else {
            G1_PASS(16); G1_PASS(20); G1_PASS(24);
        }
        __syncthreads();

        // ============ GEMM2 + fused moments ============
        ull s1a = 0ULL, s2a = 0ULL;
        if (sgrp == 0) {
            G2_PASS(0); G2_PASS(4); G2_PASS(8); G2_PASS(12);
        } else {
            G2_PASS(16); G2_PASS(20); G2_PASS(24);
        }
        // reduce moments over the 4 s-lanes (lane bits 3,4)
        s1a = fadd2(s1a, shfl_xor_ull(s1a, 8));
        s2a = fadd2(s2a, shfl_xor_ull(s2a, 8));
        s1a = fadd2(s1a, shfl_xor_ull(s1a, 16));
        s2a = fadd2(s2a, shfl_xor_ull(s2a, 16));
        if ((lane & 24) == 0) {
            *(ull*)&sP1[sgrp*64 + ll_f] = s1a;
            *(ull*)&sP2[sgrp*64 + ll_f] = s2a;
        }
        __syncthreads();

        // -------- filter update (all threads, redundant per l) --------
        float s1 = sP1[lq] + sP1[64 + lq];
        float s2 = sP2[lq] + sP2[64 + lq];
        float mp = s1 * (1.0f/25.0f);
        float Pp = Qd + s2 * (1.0f/25.0f) - mp*mp;
        float Jp = 1.0f / Pp;
        float Jf = Jp + Kv_pf;
        float Pf = 1.0f / Jf;
        float mf = Pf * (Jp*mp + kv_pf);
        float spf = sqrtf(Pf);
        if (tid < 64) {
            out[ZF_SZ + 0*M_SZ + go] = mf;
            out[ZF_SZ + 1*M_SZ + go] = mp;
            out[ZF_SZ + 2*M_SZ + go] = Pf;
            out[ZF_SZ + 3*M_SZ + go] = Pp;
        }

        // -------- z update + z_f output --------
        #pragma unroll
        for (int i = 0; i < 6; i++) {
            int idx = tid + i*NT;
            int s = idx >> 6;
            float zv = mf + spf * npf[i];
            sZ[s*ZS + lq] = zv;
            out[((s*Bn + b)*Tn + t)*Ln + lq] = zv;
        }
        if (tid < 64) {
            float zv = mf + spf * npf[6];
            sZ[24*ZS + lq] = zv;
            out[((24*Bn + b)*Tn + t)*Ln + lq] = zv;
        }
    }
}

extern "C" void kernel_launch(void* const* d_in, const int* in_sizes, int n_in,
                              void* d_out, int out_size)
{
    const float* k_in  = (const float*)d_in[0];
    const float* K_in  = (const float*)d_in[1];
    const float* noise = (const float*)d_in[2];
    const float* logQ  = (const float*)d_in[3];
    const float* m0    = (const float*)d_in[4];
    const float* logQ0 = (const float*)d_in[5];
    const float* W1    = (const float*)d_in[6];
    const float* b1    = (const float*)d_in[7];
    const float* W2    = (const float*)d_in[8];
    const float* b2    = (const float*)d_in[9];
    float* out = (float*)d_out;

    cudaFuncSetAttribute(nlf_kernel, cudaFuncAttributeMaxDynamicSharedMemorySize, SMEM_BYTES);
    nlf_kernel<<<Bn, NT, SMEM_BYTES>>>(k_in, K_in, noise, logQ, m0, logQ0,
                                       W1, b1, W2, b2, out);
}

// round 7
// speedup vs baseline: 2.3051x; 1.1638x over previous
#include <cuda_runtime.h>
#include <math.h>

#define Bn 128
#define Tn 256
#define Ln 64
#define Sn 25
#define Hn 128
#define NT 512

#define ZS  68
#define THS 132

#define ZF_SZ  52428800   // 25*128*256*64
#define M_SZ   2097152    // 128*256*64

// smem layout (floats)
#define OFF_Z   0
#define OFF_TH  (OFF_Z + 32*ZS)
#define OFF_P1  (OFF_TH + 32*THS)
#define OFF_P2  (OFF_P1 + 128)
#define SMEM_FLOATS (OFF_P2 + 128)
#define SMEM_BYTES (SMEM_FLOATS * 4)

typedef unsigned long long ull;

__device__ __forceinline__ float tanh_fast(float x) {
    float y;
    asm("tanh.approx.f32 %0, %1;" : "=f"(y) : "f"(x));
    return y;
}
__device__ __forceinline__ ull fma2(ull a, ull b, ull c) {
    ull d;
    asm("fma.rn.f32x2 %0, %1, %2, %3;" : "=l"(d) : "l"(a), "l"(b), "l"(c));
    return d;
}
__device__ __forceinline__ ull fadd2(ull a, ull b) {
    ull d;
    asm("add.rn.f32x2 %0, %1, %2;" : "=l"(d) : "l"(a), "l"(b));
    return d;
}
__device__ __forceinline__ ull pack2(float lo, float hi) {
    ull d;
    asm("mov.b64 %0, {%1, %2};" : "=l"(d) : "f"(lo), "f"(hi));
    return d;
}
__device__ __forceinline__ float2 unpack2(ull v) {
    float2 r;
    asm("mov.b64 {%0, %1}, %2;" : "=f"(r.x), "=f"(r.y) : "l"(v));
    return r;
}
__device__ __forceinline__ ull shfl_xor_ull(ull v, int m) {
    unsigned lo = (unsigned)v, hi = (unsigned)(v >> 32);
    lo = __shfl_xor_sync(0xffffffffu, lo, m);
    hi = __shfl_xor_sync(0xffffffffu, hi, m);
    return ((ull)hi << 32) | (ull)lo;
}

// ---------- GEMM1 sub-pass: warp covers 4 s-rows (s0..s0+3) x 16 h ----------
// Accumulator local index = logical index XOR lane-permutation -> select-free
// reduce-scatter: every round is  A[i] += shfl_xor(A[half+i], m).
#define G1_PASS(s0_) do {                                                     \
    ull A[8];                                                                 \
    _Pragma("unroll")                                                         \
    for (int i = 0; i < 8; i++) A[i] = 0ULL;                                  \
    _Pragma("unroll")                                                         \
    for (int si = 0; si < 4; si++) {                                          \
        const int row = (s0_) + (si ^ sperm1);                                \
        float4 a = *(const float4*)&sZ[row*ZS + K1];                          \
        float4 c = *(const float4*)&sZ[row*ZS + K1 + 4];                      \
        float av[4] = {a.x, a.y, a.z, a.w};                                   \
        float cv[4] = {c.x, c.y, c.z, c.w};                                   \
        _Pragma("unroll")                                                     \
        for (int q = 0; q < 4; q++) {                                         \
            ull zd = pack2(av[q], av[q]);                                     \
            A[si*2+0] = fma2(zd, w1r[q][0], A[si*2+0]);                       \
            A[si*2+1] = fma2(zd, w1r[q][1], A[si*2+1]);                       \
        }                                                                     \
        _Pragma("unroll")                                                     \
        for (int q = 0; q < 4; q++) {                                         \
            ull zd = pack2(cv[q], cv[q]);                                     \
            A[si*2+0] = fma2(zd, w1r[4+q][0], A[si*2+0]);                     \
            A[si*2+1] = fma2(zd, w1r[4+q][1], A[si*2+1]);                     \
        }                                                                     \
    }                                                                         \
    _Pragma("unroll")                                                         \
    for (int i = 0; i < 4; i++) A[i] = fadd2(A[i], shfl_xor_ull(A[4+i], 16)); \
    _Pragma("unroll")                                                         \
    for (int i = 0; i < 2; i++) A[i] = fadd2(A[i], shfl_xor_ull(A[2+i], 8));  \
    A[0] = fadd2(A[0], shfl_xor_ull(A[1], 4));                                \
    A[0] = fadd2(A[0], b1f);                                                  \
    float2 u = unpack2(A[0]);                                                 \
    const int sf = (s0_) + sperm1;                                            \
    *(ull*)&sTh[sf*THS + h_f] = pack2(tanh_fast(u.x), tanh_fast(u.y));        \
} while (0)

// ---------- GEMM2 sub-pass + fused moments: warp covers 4 s-rows x 8 l ------
#define G2_PASS(s0_) do {                                                     \
    ull A[8];                                                                 \
    _Pragma("unroll")                                                         \
    for (int i = 0; i < 8; i++) A[i] = 0ULL;                                  \
    _Pragma("unroll")                                                         \
    for (int si = 0; si < 4; si++) {                                          \
        const int row = (s0_) + (si ^ sperm2);                                \
        float4 a = *(const float4*)&sTh[row*THS + K2];                        \
        float4 c = *(const float4*)&sTh[row*THS + K2 + 4];                    \
        float av[4] = {a.x, a.y, a.z, a.w};                                   \
        float cv[4] = {c.x, c.y, c.z, c.w};                                   \
        _Pragma("unroll")                                                     \
        for (int q = 0; q < 4; q++) {                                         \
            ull td = pack2(av[q], av[q]);                                     \
            A[si*2+0] = fma2(td, w2r[q][0], A[si*2+0]);                       \
            A[si*2+1] = fma2(td, w2r[q][1], A[si*2+1]);                       \
        }                                                                     \
        _Pragma("unroll")                                                     \
        for (int q = 0; q < 4; q++) {                                         \
            ull td = pack2(cv[q], cv[q]);                                     \
            A[si*2+0] = fma2(td, w2r[4+q][0], A[si*2+0]);                     \
            A[si*2+1] = fma2(td, w2r[4+q][1], A[si*2+1]);                     \
        }                                                                     \
    }                                                                         \
    _Pragma("unroll")                                                         \
    for (int i = 0; i < 4; i++) A[i] = fadd2(A[i], shfl_xor_ull(A[4+i], 16)); \
    _Pragma("unroll")                                                         \
    for (int i = 0; i < 2; i++) A[i] = fadd2(A[i], shfl_xor_ull(A[2+i], 8));  \
    A[0] = fadd2(A[0], shfl_xor_ull(A[1], 4));                                \
    float2 u = unpack2(A[0]);                                                 \
    float rv = u.x + __shfl_xor_sync(0xffffffffu, u.y, 2);                    \
    const int sf = (s0_) + sperm2;                                            \
    float m = rv + b2f + sZ[sf*ZS + l_f];                                     \
    if ((s0_) == 24 && sf >= Sn) m = 0.0f;                                    \
    s1a += m;                                                                 \
    s2a = fmaf(m, m, s2a);                                                    \
} while (0)

__global__ __launch_bounds__(NT, 1)
void nlf_kernel(const float* __restrict__ k_in,
                const float* __restrict__ K_in,
                const float* __restrict__ noise,
                const float* __restrict__ logQ,
                const float* __restrict__ m0,
                const float* __restrict__ logQ0,
                const float* __restrict__ W1,
                const float* __restrict__ b1,
                const float* __restrict__ W2,
                const float* __restrict__ b2,
                float* __restrict__ out)
{
    extern __shared__ float sm[];
    float* sZ  = sm + OFF_Z;    // [32][68]  z[s][l]  (rows 25..31 stay 0)
    float* sTh = sm + OFF_TH;   // [32][132] tanh-out[s][h]
    float* sP1 = sm + OFF_P1;   // [2][64]   per-sgrp moment partial sum
    float* sP2 = sm + OFF_P2;   // [2][64]   per-sgrp moment partial sumsq

    const int tid  = threadIdx.x;
    const int b    = blockIdx.x;
    const int w    = tid >> 5;
    const int lane = tid & 31;
    const int lq   = tid & 63;   // this thread's filter l

    const int grp  = w >> 1;     // 0..7 : GEMM1 h-cluster / GEMM2 l-cluster
    const int sgrp = w & 1;      // 0: s 0..15, 1: s 16..27

    // GEMM1 lane mapping: 16 h per warp
    const int hs   = lane & 3;
    const int kg1  = lane >> 2;          // 8-way k split over 64
    const int K1   = kg1 * 8;
    const int Hb   = grp * 16;
    const int sperm1 = kg1 >> 1;         // 2-bit s permutation
    const int jperm1 = kg1 & 1;          // h-pair permutation
    const int h_f  = Hb + hs*4 + jperm1*2;

    // GEMM2 lane mapping: 8 l per warp
    const int ls   = lane & 1;
    const int kg2  = lane >> 1;          // 16-way k split over 128
    const int K2   = kg2 * 8;
    const int Lb   = grp * 8;
    const int sperm2 = kg2 >> 2;         // 2-bit s permutation
    const int jperm2 = (kg2 >> 1) & 1;   // l-pair permutation
    const int hperm2 = kg2 & 1;          // f32-half permutation
    const int l_f  = Lb + ls*4 + jperm2*2 + hperm2;

    // -------- register-resident weights (permuted order) --------
    ull w1r[8][2];
    #pragma unroll
    for (int kk = 0; kk < 8; kk++) {
        const float* p = W1 + (K1 + kk)*Hn + Hb + hs*4;
        float4 v = *(const float4*)p;
        ull p0 = pack2(v.x, v.y);
        ull p1 = pack2(v.z, v.w);
        w1r[kk][0] = jperm1 ? p1 : p0;
        w1r[kk][1] = jperm1 ? p0 : p1;
    }
    ull w2r[8][2];
    #pragma unroll
    for (int kk = 0; kk < 8; kk++) {
        const float* p = W2 + (K2 + kk)*Ln + Lb + ls*4;
        float4 v = *(const float4*)p;
        ull p0 = hperm2 ? pack2(v.y, v.x) : pack2(v.x, v.y);
        ull p1 = hperm2 ? pack2(v.w, v.z) : pack2(v.z, v.w);
        w2r[kk][0] = jperm2 ? p1 : p0;
        w2r[kk][1] = jperm2 ? p0 : p1;
    }
    const ull   b1f = pack2(b1[h_f], b1[h_f + 1]);
    const float b2f = b2[l_f];
    const float Qd  = log1pf(expf(logQ[lq]));

    // -------- init: zero z, t=0 filter --------
    for (int i = tid; i < 32*ZS; i += NT) sZ[i] = 0.0f;
    if (tid < 64) {
        int l = tid;
        float P0 = log1pf(expf(logQ0[l]));
        float J0 = 1.0f / P0;
        float h0 = J0 * m0[l];
        int  go  = (b*Tn + 0)*Ln + l;
        float Kv = K_in[go];
        float kv = k_in[go];
        float Jf = J0 + Kv;
        float Pf = 1.0f / Jf;
        float mf = Pf * (h0 + kv);
        out[ZF_SZ + 0*M_SZ + go] = mf;
        out[ZF_SZ + 1*M_SZ + go] = m0[l];
        out[ZF_SZ + 2*M_SZ + go] = Pf;
        out[ZF_SZ + 3*M_SZ + go] = P0;
        sP1[l] = mf;
        sP2[l] = sqrtf(Pf);
    }
    __syncthreads();

    // z update for t = 0
    {
        float mf = sP1[lq], spf = sP2[lq];
        #pragma unroll
        for (int i = 0; i < 3; i++) {
            int idx = tid + i*NT;
            int s = idx >> 6;
            float wn = noise[((0*Sn + s)*Bn + b)*Ln + lq];
            float zv = mf + spf * wn;
            sZ[s*ZS + lq] = zv;
            out[((s*Bn + b)*Tn + 0)*Ln + lq] = zv;
        }
        if (tid < 64) {
            float wn = noise[((0*Sn + 24)*Bn + b)*Ln + lq];
            float zv = mf + spf * wn;
            sZ[24*ZS + lq] = zv;
            out[((24*Bn + b)*Tn + 0)*Ln + lq] = zv;
        }
    }

    for (int t = 1; t < Tn; t++) {
        // -------- prefetch globals (overlap with GEMMs) --------
        float npf[4];
        #pragma unroll
        for (int i = 0; i < 3; i++) {
            int idx = tid + i*NT;
            npf[i] = noise[((t*Sn + (idx >> 6))*Bn + b)*Ln + lq];
        }
        npf[3] = (tid < 64) ? noise[((t*Sn + 24)*Bn + b)*Ln + lq] : 0.0f;
        const int go = (b*Tn + t)*Ln + lq;
        float Kv_pf = K_in[go];
        float kv_pf = k_in[go];

        __syncthreads();   // z for this step ready

        // ============ GEMM1: th = tanh(z @ W1 + b1) ============
        if (sgrp == 0) {
            G1_PASS(0); G1_PASS(4); G1_PASS(8); G1_PASS(12);
        } else {
            G1_PASS(16); G1_PASS(20); G1_PASS(24);
        }
        __syncthreads();

        // ============ GEMM2 + fused moments ============
        float s1a = 0.0f, s2a = 0.0f;
        if (sgrp == 0) {
            G2_PASS(0); G2_PASS(4); G2_PASS(8); G2_PASS(12);
        } else {
            G2_PASS(16); G2_PASS(20); G2_PASS(24);
        }
        // all-reduce moments over the 4 s-lanes (lane bits 3,4)
        s1a += __shfl_xor_sync(0xffffffffu, s1a, 8);
        s2a += __shfl_xor_sync(0xffffffffu, s2a, 8);
        s1a += __shfl_xor_sync(0xffffffffu, s1a, 16);
        s2a += __shfl_xor_sync(0xffffffffu, s2a, 16);
        if ((lane & 24) == 0) {
            sP1[sgrp*64 + l_f] = s1a;
            sP2[sgrp*64 + l_f] = s2a;
        }
        __syncthreads();

        // -------- filter update (all threads, redundant per l) --------
        float s1 = sP1[lq] + sP1[64 + lq];
        float s2 = sP2[lq] + sP2[64 + lq];
        float mp = s1 * (1.0f/25.0f);
        float Pp = Qd + s2 * (1.0f/25.0f) - mp*mp;
        float Jp = 1.0f / Pp;
        float Jf = Jp + Kv_pf;
        float Pf = 1.0f / Jf;
        float mf = Pf * (Jp*mp + kv_pf);
        float spf = sqrtf(Pf);
        if (tid < 64) {
            out[ZF_SZ + 0*M_SZ + go] = mf;
            out[ZF_SZ + 1*M_SZ + go] = mp;
            out[ZF_SZ + 2*M_SZ + go] = Pf;
            out[ZF_SZ + 3*M_SZ + go] = Pp;
        }

        // -------- z update + z_f output --------
        #pragma unroll
        for (int i = 0; i < 3; i++) {
            int idx = tid + i*NT;
            int s = idx >> 6;
            float zv = mf + spf * npf[i];
            sZ[s*ZS + lq] = zv;
            out[((s*Bn + b)*Tn + t)*Ln + lq] = zv;
        }
        if (tid < 64) {
            float zv = mf + spf * npf[3];
            sZ[24*ZS + lq] = zv;
            out[((24*Bn + b)*Tn + t)*Ln + lq] = zv;
        }
    }
}

extern "C" void kernel_launch(void* const* d_in, const int* in_sizes, int n_in,
                              void* d_out, int out_size)
{
    const float* k_in  = (const float*)d_in[0];
    const float* K_in  = (const float*)d_in[1];
    const float* noise = (const float*)d_in[2];
    const float* logQ  = (const float*)d_in[3];
    const float* m0    = (const float*)d_in[4];
    const float* logQ0 = (const float*)d_in[5];
    const float* W1    = (const float*)d_in[6];
    const float* b1    = (const float*)d_in[7];
    const float* W2    = (const float*)d_in[8];
    const float* b2    = (const float*)d_in[9];
    float* out = (float*)d_out;

    cudaFuncSetAttribute(nlf_kernel, cudaFuncAttributeMaxDynamicSharedMemorySize, SMEM_BYTES);
    nlf_kernel<<<Bn, NT, SMEM_BYTES>>>(k_in, K_in, noise, logQ, m0, logQ0,
                                       W1, b1, W2, b2, out);
}